// round 5
// baseline (speedup 1.0000x reference)
#include <cuda_runtime.h>

#define BB 2
#define CC 64
#define NN 16384
#define KK 16
#define COUT 64

// Scratch (static device globals — no allocation allowed)
__device__ float g_y1[BB * NN * CC];    // (W1-W2)·x, node-major [b][n][o]
__device__ float g_y2[BB * NN * CC];    // W2·x,      node-major [b][n][o]
__device__ float g_mean[BB * CC];       // per-batch channel means
__device__ float g_dvec[BB * COUT];     // W3·mean + bias

// ---------------------------------------------------------------------------
// Kernel 1: per-(b,c) mean over nodes. 128 blocks x 256 threads.
// ---------------------------------------------------------------------------
__global__ void mean_kernel(const float* __restrict__ x) {
    int row = blockIdx.x;                       // b*64 + c
    const float* p = x + (size_t)row * NN;
    float s = 0.f;
    for (int i = threadIdx.x; i < NN; i += 256) s += p[i];
    for (int off = 16; off; off >>= 1) s += __shfl_down_sync(0xffffffffu, s, off);
    __shared__ float red[8];
    if ((threadIdx.x & 31) == 0) red[threadIdx.x >> 5] = s;
    __syncthreads();
    if (threadIdx.x < 8) {
        s = red[threadIdx.x];
        for (int off = 4; off; off >>= 1) s += __shfl_down_sync(0xffu, s, off);
        if (threadIdx.x == 0) g_mean[row] = s * (1.f / NN);
    }
}

// ---------------------------------------------------------------------------
// Kernel 2: d[b][o] = bias[o] + sum_c W3[o][c] * mean[b][c]. 1 block, 128 thr.
// ---------------------------------------------------------------------------
__global__ void dvec_kernel(const float* __restrict__ W, const float* __restrict__ bias) {
    int t = threadIdx.x;
    if (t >= BB * COUT) return;
    int b = t >> 6, o = t & 63;
    float s = bias[o];
#pragma unroll 8
    for (int c = 0; c < CC; c++)
        s += W[o * 192 + 128 + c] * g_mean[b * CC + c];
    g_dvec[t] = s;
}

// ---------------------------------------------------------------------------
// Kernel 3: y1[b][n][o] = sum_c (W1-W2)[o][c] x[b][c][n]
//           y2[b][n][o] = sum_c  W2[o][c]     x[b][c][n]
// Tile: 128 nodes/block, 256 threads = 8 o-groups(8 outs) x 32 node-lanes,
// 4 nodes/thread to amortize W shared reads. Dynamic smem 64KB.
// ---------------------------------------------------------------------------
__global__ void __launch_bounds__(256, 1) gemm_kernel(const float* __restrict__ x,
                                                      const float* __restrict__ W) {
    extern __shared__ float sm[];
    float* xs = sm;                 // [64][128]  x tile (c-major)
    float* wa = sm + 64 * 128;      // [64][64]   W1-W2
    float* wb = wa + 64 * 64;       // [64][64]   W2

    int b  = blockIdx.x >> 7;       // 128 tiles per batch
    int n0 = (blockIdx.x & 127) << 7;
    int tid = threadIdx.x;

    for (int i = tid; i < 64 * 64; i += 256) {
        int o = i >> 6, c = i & 63;
        float w2 = W[o * 192 + 64 + c];
        wa[i] = W[o * 192 + c] - w2;
        wb[i] = w2;
    }
    const float* xb = x + (size_t)b * CC * NN + n0;
    for (int i = tid; i < 64 * 128; i += 256) {
        int c = i >> 7, nl = i & 127;
        xs[i] = xb[(size_t)c * NN + nl];    // coalesced 128-float rows
    }
    __syncthreads();

    int nl = tid & 31;              // node lane (handles nl, nl+32, nl+64, nl+96)
    int o0 = (tid >> 5) * 8;        // 8 outputs per thread

    float a1[4][8], a2[4][8];
#pragma unroll
    for (int q = 0; q < 4; q++)
#pragma unroll
        for (int j = 0; j < 8; j++) { a1[q][j] = 0.f; a2[q][j] = 0.f; }

    for (int c = 0; c < 64; c++) {
        float xv[4];
#pragma unroll
        for (int q = 0; q < 4; q++) xv[q] = xs[c * 128 + nl + q * 32];
#pragma unroll
        for (int j = 0; j < 8; j++) {
            float wav = wa[(o0 + j) * 64 + c];   // broadcast within warp
            float wbv = wb[(o0 + j) * 64 + c];
#pragma unroll
            for (int q = 0; q < 4; q++) {
                a1[q][j] += wav * xv[q];
                a2[q][j] += wbv * xv[q];
            }
        }
    }

#pragma unroll
    for (int q = 0; q < 4; q++) {
        size_t base = ((size_t)b * NN + n0 + nl + q * 32) * 64 + o0;
        float4* p1 = (float4*)&g_y1[base];
        p1[0] = make_float4(a1[q][0], a1[q][1], a1[q][2], a1[q][3]);
        p1[1] = make_float4(a1[q][4], a1[q][5], a1[q][6], a1[q][7]);
        float4* p2 = (float4*)&g_y2[base];
        p2[0] = make_float4(a2[q][0], a2[q][1], a2[q][2], a2[q][3]);
        p2[1] = make_float4(a2[q][4], a2[q][5], a2[q][6], a2[q][7]);
    }
}

// ---------------------------------------------------------------------------
// Kernel 4: gather + max over K + bias + relu.
// 32 nodes/block, 256 threads = 64 channels x 4 node-groups.
// Each gather is a contiguous 256B read (node-major y). Output staged in smem
// for coalesced channel-major stores.
// NOTE: edge_index is int32 on device (JAX x64 disabled downcasts int64).
// Indices masked to [0,NN) — turns any dtype surprise into a rel_err signal
// instead of an illegal access. Free under the latency-bound gather loop.
// ---------------------------------------------------------------------------
__global__ void __launch_bounds__(256, 1) gather_kernel(const int* __restrict__ ei,
                                                        float* __restrict__ out) {
    __shared__ int s_i0[32 * KK];
    __shared__ int s_i1[32 * KK];
    __shared__ float s_out[64][33];

    int b  = blockIdx.x >> 9;           // 512 tiles per batch
    int n0 = (blockIdx.x & 511) << 5;
    int tid = threadIdx.x;

    const int* e0 = ei + ((size_t)b * NN + n0) * KK;            // edge_index[0][b] (neighbor)
    const int* e1 = ei + ((size_t)(BB + b) * NN + n0) * KK;     // edge_index[1][b] (center)
    for (int i = tid; i < 32 * KK; i += 256) {
        s_i0[i] = e0[i] & (NN - 1);
        s_i1[i] = e1[i] & (NN - 1);
    }
    __syncthreads();

    int o  = tid & 63;
    int lg = tid >> 6;
    const float* y1 = g_y1 + (size_t)b * NN * 64;
    const float* y2 = g_y2 + (size_t)b * NN * 64;

    for (int nl = lg; nl < 32; nl += 4) {
        float m = -3.4e38f;
#pragma unroll
        for (int k = 0; k < KK; k++) {
            int j1 = s_i1[nl * KK + k];
            int j0 = s_i0[nl * KK + k];
            m = fmaxf(m, __ldg(&y1[(size_t)j1 * 64 + o]) + __ldg(&y2[(size_t)j0 * 64 + o]));
        }
        s_out[o][nl] = m;
    }
    __syncthreads();

    float* ob = out + (size_t)b * COUT * NN + n0;
    for (int i = tid; i < 64 * 32; i += 256) {
        int o2 = i >> 5, nl2 = i & 31;
        float v = s_out[o2][nl2] + g_dvec[b * 64 + o2];
        ob[(size_t)o2 * NN + nl2] = fmaxf(v, 0.f);   // relu(max) == max(relu)
    }
}

// ---------------------------------------------------------------------------
extern "C" void kernel_launch(void* const* d_in, const int* in_sizes, int n_in,
                              void* d_out, int out_size) {
    const float* x    = (const float*)d_in[0];
    const int*   ei   = (const int*)d_in[1];
    const float* W    = (const float*)d_in[2];
    const float* bias = (const float*)d_in[3];
    float*       out  = (float*)d_out;

    cudaFuncSetAttribute(gemm_kernel, cudaFuncAttributeMaxDynamicSharedMemorySize, 65536);

    mean_kernel<<<BB * CC, 256>>>(x);
    dvec_kernel<<<1, 128>>>(W, bias);
    gemm_kernel<<<BB * (NN / 128), 256, 65536>>>(x, W);
    gather_kernel<<<BB * (NN / 32), 256>>>(ei, out);
}

// round 7
// speedup vs baseline: 1.7351x; 1.7351x over previous
#include <cuda_runtime.h>

#define BB 2
#define CC 64
#define NN 16384
#define KK 16
#define COUT 64

// Scratch (static device globals — no allocation allowed)
__device__ float g_y1[BB * NN * CC];    // (W1-W2)·x, node-major [b][n][o]
__device__ float g_y2[BB * NN * CC];    // W2·x,      node-major [b][n][o]
__device__ float g_mean[BB * CC];       // per-batch channel means
__device__ float g_dvec[BB * COUT];     // W3·mean + bias

// ---------------------------------------------------------------------------
// Kernel 1: per-(b,c) mean over nodes. 128 blocks x 256 threads.
// ---------------------------------------------------------------------------
__global__ void mean_kernel(const float* __restrict__ x) {
    int row = blockIdx.x;                       // b*64 + c
    const float* p = x + (size_t)row * NN;
    float s = 0.f;
    for (int i = threadIdx.x; i < NN; i += 256) s += p[i];
    for (int off = 16; off; off >>= 1) s += __shfl_down_sync(0xffffffffu, s, off);
    __shared__ float red[8];
    if ((threadIdx.x & 31) == 0) red[threadIdx.x >> 5] = s;
    __syncthreads();
    if (threadIdx.x < 8) {
        s = red[threadIdx.x];
        for (int off = 4; off; off >>= 1) s += __shfl_down_sync(0xffu, s, off);
        if (threadIdx.x == 0) g_mean[row] = s * (1.f / NN);
    }
}

// ---------------------------------------------------------------------------
// Kernel 2: d[b][o] = bias[o] + sum_c W3[o][c] * mean[b][c]. 1 block, 128 thr.
// ---------------------------------------------------------------------------
__global__ void dvec_kernel(const float* __restrict__ W, const float* __restrict__ bias) {
    int t = threadIdx.x;
    if (t >= BB * COUT) return;
    int b = t >> 6, o = t & 63;
    float s = bias[o];
#pragma unroll 8
    for (int c = 0; c < CC; c++)
        s += W[o * 192 + 128 + c] * g_mean[b * CC + c];
    g_dvec[t] = s;
}

// ---------------------------------------------------------------------------
// Kernel 3: y1[b][n][o] = sum_c (W1-W2)[o][c] x[b][c][n]
//           y2[b][n][o] = sum_c  W2[o][c]     x[b][c][n]
// ---------------------------------------------------------------------------
__global__ void __launch_bounds__(256, 1) gemm_kernel(const float* __restrict__ x,
                                                      const float* __restrict__ W) {
    extern __shared__ float sm[];
    float* xs = sm;                 // [64][128]  x tile (c-major)
    float* wa = sm + 64 * 128;      // [64][64]   W1-W2
    float* wb = wa + 64 * 64;       // [64][64]   W2

    int b  = blockIdx.x >> 7;       // 128 tiles per batch
    int n0 = (blockIdx.x & 127) << 7;
    int tid = threadIdx.x;

    for (int i = tid; i < 64 * 64; i += 256) {
        int o = i >> 6, c = i & 63;
        float w2 = W[o * 192 + 64 + c];
        wa[i] = W[o * 192 + c] - w2;
        wb[i] = w2;
    }
    const float* xb = x + (size_t)b * CC * NN + n0;
    for (int i = tid; i < 64 * 128; i += 256) {
        int c = i >> 7, nl = i & 127;
        xs[i] = xb[(size_t)c * NN + nl];    // coalesced 128-float rows
    }
    __syncthreads();

    int nl = tid & 31;              // node lane (handles nl, nl+32, nl+64, nl+96)
    int o0 = (tid >> 5) * 8;        // 8 outputs per thread

    float a1[4][8], a2[4][8];
#pragma unroll
    for (int q = 0; q < 4; q++)
#pragma unroll
        for (int j = 0; j < 8; j++) { a1[q][j] = 0.f; a2[q][j] = 0.f; }

    for (int c = 0; c < 64; c++) {
        float xv[4];
#pragma unroll
        for (int q = 0; q < 4; q++) xv[q] = xs[c * 128 + nl + q * 32];
#pragma unroll
        for (int j = 0; j < 8; j++) {
            float wav = wa[(o0 + j) * 64 + c];   // broadcast within warp
            float wbv = wb[(o0 + j) * 64 + c];
#pragma unroll
            for (int q = 0; q < 4; q++) {
                a1[q][j] += wav * xv[q];
                a2[q][j] += wbv * xv[q];
            }
        }
    }

#pragma unroll
    for (int q = 0; q < 4; q++) {
        size_t base = ((size_t)b * NN + n0 + nl + q * 32) * 64 + o0;
        float4* p1 = (float4*)&g_y1[base];
        p1[0] = make_float4(a1[q][0], a1[q][1], a1[q][2], a1[q][3]);
        p1[1] = make_float4(a1[q][4], a1[q][5], a1[q][6], a1[q][7]);
        float4* p2 = (float4*)&g_y2[base];
        p2[0] = make_float4(a2[q][0], a2[q][1], a2[q][2], a2[q][3]);
        p2[1] = make_float4(a2[q][4], a2[q][5], a2[q][6], a2[q][7]);
    }
}

// ---------------------------------------------------------------------------
// Kernel 4 (v2): gather + max over K + bias + relu — float4 vectorized.
// 64-node tile / block, 256 threads = 16 float4-channel lanes x 16 node groups.
// 4x fewer LDG + index-ALU vs v1 (attacks measured ALU=47%/issue=59% bound).
// Indices premultiplied (<<4 = float4 row stride) in smem; full-K unroll for MLP.
// Output staged in smem, stored as coalesced float4 channel-major rows with
// dvec + relu fused.
// ---------------------------------------------------------------------------
__global__ void __launch_bounds__(256, 4) gather_kernel(const int* __restrict__ ei,
                                                        float* __restrict__ out) {
    __shared__ int   s_j0[64 * KK];
    __shared__ int   s_j1[64 * KK];
    __shared__ float s_out[64][66];     // [channel][node], padded

    int b   = blockIdx.x >> 8;          // 256 tiles per batch
    int n0  = (blockIdx.x & 255) << 6;
    int tid = threadIdx.x;

    const int* e0 = ei + ((size_t)b * NN + n0) * KK;            // neighbors (edge_index[0])
    const int* e1 = ei + ((size_t)(BB + b) * NN + n0) * KK;     // centers   (edge_index[1])
    for (int i = tid; i < 64 * KK; i += 256) {
        s_j0[i] = (e0[i] & (NN - 1)) << 4;   // float4-row offset
        s_j1[i] = (e1[i] & (NN - 1)) << 4;
    }
    __syncthreads();

    int f4 = tid & 15;                  // which float4 of the 64-channel row
    int ng = tid >> 4;                  // node group 0..15
    const float4* y1 = (const float4*)g_y1 + (size_t)b * NN * 16;
    const float4* y2 = (const float4*)g_y2 + (size_t)b * NN * 16;

#pragma unroll
    for (int nl = ng; nl < 64; nl += 16) {
        float4 m = make_float4(-3.4e38f, -3.4e38f, -3.4e38f, -3.4e38f);
        const int* pj1 = &s_j1[nl * KK];
        const int* pj0 = &s_j0[nl * KK];
#pragma unroll
        for (int k = 0; k < KK; k++) {
            float4 a = __ldg(y1 + pj1[k] + f4);
            float4 c = __ldg(y2 + pj0[k] + f4);
            m.x = fmaxf(m.x, a.x + c.x);
            m.y = fmaxf(m.y, a.y + c.y);
            m.z = fmaxf(m.z, a.z + c.z);
            m.w = fmaxf(m.w, a.w + c.w);
        }
        int o0 = f4 * 4;
        s_out[o0 + 0][nl] = m.x;
        s_out[o0 + 1][nl] = m.y;
        s_out[o0 + 2][nl] = m.z;
        s_out[o0 + 3][nl] = m.w;
    }
    __syncthreads();

    float* ob = out + (size_t)b * COUT * NN + n0;
    for (int i = tid; i < 64 * 16; i += 256) {       // 64 channels x 16 float4
        int o2 = i >> 4, q = i & 15;
        float d = g_dvec[b * 64 + o2];
        int nb = q * 4;
        float4 v;
        v.x = fmaxf(s_out[o2][nb + 0] + d, 0.f);
        v.y = fmaxf(s_out[o2][nb + 1] + d, 0.f);
        v.z = fmaxf(s_out[o2][nb + 2] + d, 0.f);
        v.w = fmaxf(s_out[o2][nb + 3] + d, 0.f);
        *(float4*)(ob + (size_t)o2 * NN + nb) = v;   // n0 mult of 64 -> 16B aligned
    }
}

// ---------------------------------------------------------------------------
extern "C" void kernel_launch(void* const* d_in, const int* in_sizes, int n_in,
                              void* d_out, int out_size) {
    const float* x    = (const float*)d_in[0];
    const int*   ei   = (const int*)d_in[1];
    const float* W    = (const float*)d_in[2];
    const float* bias = (const float*)d_in[3];
    float*       out  = (float*)d_out;

    cudaFuncSetAttribute(gemm_kernel, cudaFuncAttributeMaxDynamicSharedMemorySize, 65536);

    mean_kernel<<<BB * CC, 256>>>(x);
    dvec_kernel<<<1, 128>>>(W, bias);
    gemm_kernel<<<BB * (NN / 128), 256, 65536>>>(x, W);
    gather_kernel<<<BB * (NN / 64), 256>>>(ei, out);
}